// round 5
// baseline (speedup 1.0000x reference)
#include <cuda_runtime.h>

// Problem constants
#define B_TOT   4096
#define T_STEPS 512
#define D_IN    6
#define H_DIM   32
#define NB      4              // batch elements per warp (per-lane replication)
#define WARPS   8
#define NTHREADS (WARPS * 32)
#define NBLOCKS  (B_TOT / (WARPS * NB))   // 128

__device__ __forceinline__ float sigm(float x) {
    return __fdividef(1.0f, 1.0f + __expf(-x));
}
__device__ __forceinline__ float tanh_(float x) {
    // stable, accurate (~1e-7 abs): tanh(|x|) = (1-e^{-2|x|})/(1+e^{-2|x|})
    float a = fabsf(x);
    float e = __expf(-2.0f * a);
    float r = (1.0f - e) * __fdividef(1.0f, 1.0f + e);
    return copysignf(r, x);
}

// acc a[4] (float4 = 4 gates), one FMA bundle for a weight float4 and 4 batch h-scalars
#define FMA16(w, hv0, hv1, hv2, hv3)                              \
    a[0].x = fmaf(w.x, hv0, a[0].x); a[0].y = fmaf(w.y, hv0, a[0].y); \
    a[0].z = fmaf(w.z, hv0, a[0].z); a[0].w = fmaf(w.w, hv0, a[0].w); \
    a[1].x = fmaf(w.x, hv1, a[1].x); a[1].y = fmaf(w.y, hv1, a[1].y); \
    a[1].z = fmaf(w.z, hv1, a[1].z); a[1].w = fmaf(w.w, hv1, a[1].w); \
    a[2].x = fmaf(w.x, hv2, a[2].x); a[2].y = fmaf(w.y, hv2, a[2].y); \
    a[2].z = fmaf(w.z, hv2, a[2].z); a[2].w = fmaf(w.w, hv2, a[2].w); \
    a[3].x = fmaf(w.x, hv3, a[3].x); a[3].y = fmaf(w.y, hv3, a[3].y); \
    a[3].z = fmaf(w.z, hv3, a[3].z); a[3].w = fmaf(w.w, hv3, a[3].w);

// 32-wide matvec: acc[gate] += sum_k W[k][j][gate] * h[nb][k]
// W: float4[32*32] laid out [k][j]; HS: float4 view of h[nb][32] (8 float4 per nb)
#define MATVEC32(WARR, HS)                                                     \
    _Pragma("unroll")                                                          \
    for (int k4 = 0; k4 < 8; ++k4) {                                           \
        float4 hv0 = (HS)[0 * 8 + k4];                                         \
        float4 hv1 = (HS)[1 * 8 + k4];                                         \
        float4 hv2 = (HS)[2 * 8 + k4];                                         \
        float4 hv3 = (HS)[3 * 8 + k4];                                         \
        float4 w;                                                              \
        w = (WARR)[(k4 * 4 + 0) * 32 + j]; FMA16(w, hv0.x, hv1.x, hv2.x, hv3.x) \
        w = (WARR)[(k4 * 4 + 1) * 32 + j]; FMA16(w, hv0.y, hv1.y, hv2.y, hv3.y) \
        w = (WARR)[(k4 * 4 + 2) * 32 + j]; FMA16(w, hv0.z, hv1.z, hv2.z, hv3.z) \
        w = (WARR)[(k4 * 4 + 3) * 32 + j]; FMA16(w, hv0.w, hv1.w, hv2.w, hv3.w) \
    }

extern __shared__ float4 smem4[];

__global__ void __launch_bounds__(NTHREADS, 1) lstm2_ln_kernel(
    const float* __restrict__ x,
    const float* __restrict__ Wih0, const float* __restrict__ Whh0,
    const float* __restrict__ bih0, const float* __restrict__ bhh0,
    const float* __restrict__ Wih1, const float* __restrict__ Whh1,
    const float* __restrict__ bih1, const float* __restrict__ bhh1,
    const float* __restrict__ gamma, const float* __restrict__ beta,
    float* __restrict__ out)
{
    // Shared layout (float4 units):
    float4* whh0 = smem4;           // 1024  (16 KB)  [k][j] -> 4 gates
    float4* wih1 = smem4 + 1024;    // 1024
    float4* whh1 = smem4 + 2048;    // 1024
    float4* wih0 = smem4 + 3072;    // 192   (3 KB)   [d][j] -> 4 gates
    float4* b0s  = smem4 + 3264;    // 32
    float4* b1s  = smem4 + 3296;    // 32
    float*  h0f  = (float*)(smem4 + 3328);  // 8 warps * 4 nb * 32 = 1024 f (256 f4)
    float*  h1f  = (float*)(smem4 + 3584);  // same
    // total = 3840 float4 = 61440 bytes

    const int tid = threadIdx.x;

    // ---- stage weights into SMEM, transposed to [k][j][gate] ----
    {
        float* w0 = (float*)whh0;
        float* w1 = (float*)wih1;
        float* w2 = (float*)whh1;
        for (int idx = tid; idx < 4096; idx += NTHREADS) {
            int r = idx >> 5;        // row = g*32+j
            int k = idx & 31;
            int g = r >> 5, jj = r & 31;
            int dst = (k * 32 + jj) * 4 + g;
            w0[dst] = Whh0[idx];
            w1[dst] = Wih1[idx];
            w2[dst] = Whh1[idx];
        }
        float* wi0 = (float*)wih0;
        for (int idx = tid; idx < 128 * D_IN; idx += NTHREADS) {
            int r = idx / D_IN;
            int d = idx - r * D_IN;
            int g = r >> 5, jj = r & 31;
            wi0[(d * 32 + jj) * 4 + g] = Wih0[idx];
        }
        if (tid < 128) {
            int g = tid >> 5, jj = tid & 31;
            ((float*)b0s)[jj * 4 + g] = bih0[tid] + bhh0[tid];
            ((float*)b1s)[jj * 4 + g] = bih1[tid] + bhh1[tid];
        }
        for (int idx = tid; idx < WARPS * NB * 32; idx += NTHREADS) {
            h0f[idx] = 0.0f;
            h1f[idx] = 0.0f;
        }
    }
    __syncthreads();

    const int warp = tid >> 5;
    const int j    = tid & 31;
    const int bbase = (blockIdx.x * WARPS + warp) * NB;

    const float4 bias0 = b0s[j];
    const float4 bias1 = b1s[j];

    float h0[NB] = {0.f, 0.f, 0.f, 0.f}, c0[NB] = {0.f, 0.f, 0.f, 0.f};
    float h1[NB] = {0.f, 0.f, 0.f, 0.f}, c1[NB] = {0.f, 0.f, 0.f, 0.f};

    float*        myh0f = h0f + warp * NB * 32;
    float*        myh1f = h1f + warp * NB * 32;
    const float4* myh0  = (const float4*)myh0f;
    const float4* myh1  = (const float4*)myh1f;

    for (int t = 0; t < T_STEPS; ++t) {
        // ---- load x_t for the 4 batch elements (broadcast across lanes) ----
        float xv[NB][D_IN];
        #pragma unroll
        for (int nb = 0; nb < NB; ++nb) {
            const float2* xp = (const float2*)(x + ((size_t)(bbase + nb) * T_STEPS + t) * D_IN);
            float2 p0 = __ldg(xp);
            float2 p1 = __ldg(xp + 1);
            float2 p2 = __ldg(xp + 2);
            xv[nb][0] = p0.x; xv[nb][1] = p0.y;
            xv[nb][2] = p1.x; xv[nb][3] = p1.y;
            xv[nb][4] = p2.x; xv[nb][5] = p2.y;
        }

        float4 a[NB];

        // ================= Layer 0 =================
        #pragma unroll
        for (int nb = 0; nb < NB; ++nb) a[nb] = bias0;

        #pragma unroll
        for (int d = 0; d < D_IN; ++d) {
            float4 w = wih0[d * 32 + j];
            FMA16(w, xv[0][d], xv[1][d], xv[2][d], xv[3][d])
        }
        MATVEC32(whh0, myh0)

        #pragma unroll
        for (int nb = 0; nb < NB; ++nb) {
            float ii = sigm(a[nb].x);
            float ff = sigm(a[nb].y);
            float gg = tanh_(a[nb].z);
            float oo = sigm(a[nb].w);
            c0[nb] = fmaf(ff, c0[nb], ii * gg);
            h0[nb] = oo * tanh_(c0[nb]);
        }
        __syncwarp();
        #pragma unroll
        for (int nb = 0; nb < NB; ++nb) myh0f[nb * 32 + j] = h0[nb];
        __syncwarp();

        // ================= Layer 1 =================
        #pragma unroll
        for (int nb = 0; nb < NB; ++nb) a[nb] = bias1;

        MATVEC32(wih1, myh0)   // input = fresh h0
        MATVEC32(whh1, myh1)   // recurrent = previous h1

        #pragma unroll
        for (int nb = 0; nb < NB; ++nb) {
            float ii = sigm(a[nb].x);
            float ff = sigm(a[nb].y);
            float gg = tanh_(a[nb].z);
            float oo = sigm(a[nb].w);
            c1[nb] = fmaf(ff, c1[nb], ii * gg);
            h1[nb] = oo * tanh_(c1[nb]);
        }
        __syncwarp();
        #pragma unroll
        for (int nb = 0; nb < NB; ++nb) myh1f[nb * 32 + j] = h1[nb];
        __syncwarp();
    }

    // ---- LayerNorm over the last h1 (per batch element, across the 32 lanes) ----
    const float gj = gamma[j];
    const float bj = beta[j];
    #pragma unroll
    for (int nb = 0; nb < NB; ++nb) {
        float v = h1[nb];
        float s = v;
        #pragma unroll
        for (int o = 16; o > 0; o >>= 1) s += __shfl_xor_sync(0xffffffffu, s, o);
        float mean = s * (1.0f / 32.0f);
        float dv = v - mean;
        float q = dv * dv;
        #pragma unroll
        for (int o = 16; o > 0; o >>= 1) q += __shfl_xor_sync(0xffffffffu, q, o);
        float var = q * (1.0f / 32.0f);
        float inv = rsqrtf(var + 1e-5f);
        out[(size_t)(bbase + nb) * H_DIM + j] = fmaf(dv * inv, gj, bj);
    }
}

extern "C" void kernel_launch(void* const* d_in, const int* in_sizes, int n_in,
                              void* d_out, int out_size)
{
    const float* x     = (const float*)d_in[0];
    const float* Wih0  = (const float*)d_in[1];
    const float* Whh0  = (const float*)d_in[2];
    const float* bih0  = (const float*)d_in[3];
    const float* bhh0  = (const float*)d_in[4];
    const float* Wih1  = (const float*)d_in[5];
    const float* Whh1  = (const float*)d_in[6];
    const float* bih1  = (const float*)d_in[7];
    const float* bhh1  = (const float*)d_in[8];
    const float* gamma = (const float*)d_in[9];
    const float* beta  = (const float*)d_in[10];
    float* out = (float*)d_out;

    const int smem_bytes = 3840 * 16;  // 61440
    static int attr_set = 0;
    if (!attr_set) {
        cudaFuncSetAttribute(lstm2_ln_kernel,
                             cudaFuncAttributeMaxDynamicSharedMemorySize, smem_bytes);
        attr_set = 1;
    }

    lstm2_ln_kernel<<<NBLOCKS, NTHREADS, smem_bytes>>>(
        x, Wih0, Whh0, bih0, bhh0, Wih1, Whh1, bih1, bhh1, gamma, beta, out);
}